// round 2
// baseline (speedup 1.0000x reference)
#include <cuda_runtime.h>
#include <cuda_fp16.h>
#include <mma.h>

using namespace nvcuda;

// Problem shapes
#define BB 4
#define NN 1024
#define NBR 32
#define CC 384
#define CZDIM 128
constexpr int BN = BB * NN;      // 4096 (b,n) pairs
constexpr int NPC = 4;           // n-pairs per CTA
constexpr int ROWS = NPC * NBR;  // 128 neighbor rows per CTA

// Scratch (static device allocations are allowed)
__device__ __half g_Ws[CC * CC];
__device__ __half g_Wz[CZDIM * CC];
__device__ float  g_snew[(size_t)BN * CC];

// ---------------- weight fp32 -> fp16 conversion ----------------
__global__ void convert_w(const float* __restrict__ Ws, const float* __restrict__ Wz) {
    int i = blockIdx.x * blockDim.x + threadIdx.x;
    if (i < CC * CC)    g_Ws[i] = __float2half_rn(Ws[i]);
    if (i < CZDIM * CC) g_Wz[i] = __float2half_rn(Wz[i]);
}

// ---------------- smem layout ----------------
constexpr int A_STRIDE = 392;   // 384 + 8 pad (conflict-free ldsm)
constexpr int Z_STRIDE = 136;   // 128 + 8
constexpr int W_STRIDE = 136;   // 128 + 8
constexpr int G_STRIDE = 132;   // fp32, 128 + 4
constexpr int P_STRIDE = 20;    // fp32 slab, 16 + 4
constexpr int KBLK = 32;        // W staging depth

constexpr size_t OFF_A  = 0;
constexpr size_t OFF_Z  = OFF_A  + (size_t)ROWS * A_STRIDE * 2;         // 100352
constexpr size_t OFF_W  = OFF_Z  + (size_t)ROWS * Z_STRIDE * 2;         // +34816
constexpr size_t OFF_G  = OFF_W  + (size_t)KBLK * W_STRIDE * 2;         // +8704
constexpr size_t OFF_P  = OFF_G  + (size_t)ROWS * G_STRIDE * 4;         // +67584
constexpr size_t OFF_SI = OFF_P  + (size_t)ROWS * P_STRIDE * 4;         // +10240
constexpr size_t OFF_M  = OFF_SI + (size_t)NPC * CC * 4;                // +6144
constexpr size_t SMEM_TOTAL = OFF_M + (size_t)ROWS * 4;                 // 228352 B

// ---------------- fused main kernel ----------------
__global__ void __launch_bounds__(256) fused_kernel(
    const float* __restrict__ s_i,
    const float* __restrict__ s_ij,
    const float* __restrict__ m_ij,
    const float* __restrict__ z_ij)
{
    extern __shared__ char smem[];
    __half* A_h  = (__half*)(smem + OFF_A);
    __half* Z_h  = (__half*)(smem + OFF_Z);
    __half* W_h  = (__half*)(smem + OFF_W);
    float*  G_s  = (float*)(smem + OFF_G);
    float*  P_s  = (float*)(smem + OFF_P);
    float*  SI_s = (float*)(smem + OFF_SI);
    float*  M_s  = (float*)(smem + OFF_M);

    const int tid  = threadIdx.x;
    const int warp = tid >> 5;
    const int bn0  = blockIdx.x * NPC;

    // ---- load & convert A = s_ij rows (128 x 384) fp32 -> fp16
    {
        const float4* gA = (const float4*)(s_ij + (size_t)bn0 * NBR * CC);
        for (int idx = tid; idx < ROWS * CC / 4; idx += 256) {
            int r = idx / (CC / 4), c4 = idx % (CC / 4);
            float4 v = gA[idx];
            __half2* dst = (__half2*)(A_h + r * A_STRIDE + c4 * 4);
            dst[0] = __floats2half2_rn(v.x, v.y);
            dst[1] = __floats2half2_rn(v.z, v.w);
        }
    }
    // ---- load & convert Z = z_ij rows (128 x 128)
    {
        const float4* gZ = (const float4*)(z_ij + (size_t)bn0 * NBR * CZDIM);
        for (int idx = tid; idx < ROWS * CZDIM / 4; idx += 256) {
            int r = idx >> 5, c4 = idx & 31;
            float4 v = gZ[idx];
            __half2* dst = (__half2*)(Z_h + r * Z_STRIDE + c4 * 4);
            dst[0] = __floats2half2_rn(v.x, v.y);
            dst[1] = __floats2half2_rn(v.z, v.w);
        }
    }
    // ---- s_i (4 x 384) fp32
    {
        const float4* gS = (const float4*)(s_i + (size_t)bn0 * CC);
        for (int idx = tid; idx < NPC * CC / 4; idx += 256)
            ((float4*)SI_s)[idx] = gS[idx];
    }
    // ---- mask (128)
    if (tid < ROWS) M_s[tid] = m_ij[(size_t)bn0 * NBR + tid];
    __syncthreads();

    wmma::fragment<wmma::matrix_a, 16, 16, 16, __half, wmma::row_major> af;
    wmma::fragment<wmma::matrix_b, 16, 16, 16, __half, wmma::row_major> bf;
    wmma::fragment<wmma::accumulator, 16, 16, 16, float> cf[8];

    const int en  = tid >> 6;          // n within CTA   (epilogue role)
    const int edc = (tid >> 2) & 15;   // d-col in slab
    const int eks = tid & 3;           // k-quarter

    for (int dt = 0; dt < 3; dt++) {
        const int d0 = dt * 128;

        // ======== GEMM2: G = Z(128x128) @ Wz[:, d0:d0+128] ========
        #pragma unroll
        for (int i = 0; i < 8; i++) wmma::fill_fragment(cf[i], 0.0f);

        for (int kb = 0; kb < CZDIM / KBLK; kb++) {
            for (int idx = tid; idx < KBLK * 16; idx += 256) {   // 32 rows x 16 int4
                int kk = idx >> 4, c8 = idx & 15;
                const int4* src = (const int4*)(g_Wz + (size_t)(kb * KBLK + kk) * CC + d0) + c8;
                *((int4*)(W_h + kk * W_STRIDE) + c8) = *src;
            }
            __syncthreads();
            #pragma unroll
            for (int kk16 = 0; kk16 < 2; kk16++) {
                wmma::load_matrix_sync(af, Z_h + (warp * 16) * Z_STRIDE + kb * KBLK + kk16 * 16, Z_STRIDE);
                #pragma unroll
                for (int nf = 0; nf < 8; nf++) {
                    wmma::load_matrix_sync(bf, W_h + (kk16 * 16) * W_STRIDE + nf * 16, W_STRIDE);
                    wmma::mma_sync(cf[nf], af, bf, cf[nf]);
                }
            }
            __syncthreads();
        }
        #pragma unroll
        for (int nf = 0; nf < 8; nf++)
            wmma::store_matrix_sync(G_s + (warp * 16) * G_STRIDE + nf * 16, cf[nf],
                                    G_STRIDE, wmma::mem_row_major);
        __syncthreads();

        // ======== GEMM1: P = A(128x384) @ Ws[:, d0:d0+128] ========
        #pragma unroll
        for (int i = 0; i < 8; i++) wmma::fill_fragment(cf[i], 0.0f);

        for (int kb = 0; kb < CC / KBLK; kb++) {
            for (int idx = tid; idx < KBLK * 16; idx += 256) {
                int kk = idx >> 4, c8 = idx & 15;
                const int4* src = (const int4*)(g_Ws + (size_t)(kb * KBLK + kk) * CC + d0) + c8;
                *((int4*)(W_h + kk * W_STRIDE) + c8) = *src;
            }
            __syncthreads();
            #pragma unroll
            for (int kk16 = 0; kk16 < 2; kk16++) {
                wmma::load_matrix_sync(af, A_h + (warp * 16) * A_STRIDE + kb * KBLK + kk16 * 16, A_STRIDE);
                #pragma unroll
                for (int nf = 0; nf < 8; nf++) {
                    wmma::load_matrix_sync(bf, W_h + (kk16 * 16) * W_STRIDE + nf * 16, W_STRIDE);
                    wmma::mma_sync(cf[nf], af, bf, cf[nf]);
                }
            }
            __syncthreads();
        }

        // ======== epilogue: out[n,d] = sum_k m*(P - s_i)*G, slab by slab ========
        for (int j = 0; j < 8; j++) {
            wmma::store_matrix_sync(P_s + (warp * 16) * P_STRIDE, cf[j],
                                    P_STRIDE, wmma::mem_row_major);
            __syncthreads();

            const float sival = SI_s[en * CC + d0 + j * 16 + edc];
            float acc = 0.0f;
            const int rbase = en * 32 + eks * 8;
            #pragma unroll
            for (int kk = 0; kk < 8; kk++) {
                int r = rbase + kk;
                acc += M_s[r] * (P_s[r * P_STRIDE + edc] - sival)
                              * G_s[r * G_STRIDE + j * 16 + edc];
            }
            acc += __shfl_xor_sync(0xffffffffu, acc, 1);
            acc += __shfl_xor_sync(0xffffffffu, acc, 2);
            if (eks == 0)
                g_snew[(size_t)(bn0 + en) * CC + d0 + j * 16 + edc] = acc;
            __syncthreads();
        }
    }
}

// ---------------- layernorm ----------------
__global__ void __launch_bounds__(128) ln_kernel(
    const float* __restrict__ gamma, const float* __restrict__ beta,
    float* __restrict__ out)
{
    const int row = blockIdx.x;
    const int t   = threadIdx.x;
    const float* x = g_snew + (size_t)row * CC;
    float v0 = x[t], v1 = x[t + 128], v2 = x[t + 256];
    float s  = v0 + v1 + v2;
    float sq = v0 * v0 + v1 * v1 + v2 * v2;
    #pragma unroll
    for (int o = 16; o; o >>= 1) {
        s  += __shfl_xor_sync(0xffffffffu, s,  o);
        sq += __shfl_xor_sync(0xffffffffu, sq, o);
    }
    __shared__ float ss[4], ssq[4];
    int w = t >> 5;
    if ((t & 31) == 0) { ss[w] = s; ssq[w] = sq; }
    __syncthreads();
    s  = ss[0]  + ss[1]  + ss[2]  + ss[3];
    sq = ssq[0] + ssq[1] + ssq[2] + ssq[3];
    const float mu   = s * (1.0f / CC);
    const float var  = sq * (1.0f / CC) - mu * mu;
    const float rstd = rsqrtf(var + 1e-6f);
    float* o_ = out + (size_t)row * CC;
    o_[t]       = (v0 - mu) * rstd * gamma[t]       + beta[t];
    o_[t + 128] = (v1 - mu) * rstd * gamma[t + 128] + beta[t + 128];
    o_[t + 256] = (v2 - mu) * rstd * gamma[t + 256] + beta[t + 256];
}

// ---------------- launch ----------------
extern "C" void kernel_launch(void* const* d_in, const int* in_sizes, int n_in,
                              void* d_out, int out_size)
{
    const float* s_i   = (const float*)d_in[0];
    const float* s_ij  = (const float*)d_in[1];
    const float* m_ij  = (const float*)d_in[2];
    const float* z_ij  = (const float*)d_in[3];
    const float* W_s   = (const float*)d_in[4];
    const float* W_z   = (const float*)d_in[5];
    const float* gamma = (const float*)d_in[6];
    const float* beta  = (const float*)d_in[7];
    float* out = (float*)d_out;

    cudaFuncSetAttribute(fused_kernel, cudaFuncAttributeMaxDynamicSharedMemorySize,
                         (int)SMEM_TOTAL);

    convert_w<<<(CC * CC + 255) / 256, 256>>>(W_s, W_z);
    fused_kernel<<<BN / NPC, 256, SMEM_TOTAL>>>(s_i, s_ij, m_ij, z_ij);
    ln_kernel<<<BN, 128>>>(gamma, beta, out);
}

// round 5
// speedup vs baseline: 2.1105x; 2.1105x over previous
#include <cuda_runtime.h>
#include <cuda_fp16.h>
#include <cstdint>

// ---------------- problem shapes ----------------
constexpr int NBR = 32;
constexpr int CC  = 384;
constexpr int CZ  = 128;
constexpr int NPC = 4;            // (b,n) pairs per CTA
constexpr int ROWS = NPC * NBR;   // 128 = M
constexpr int BN = 4096;

// transposed fp16 weights: [d][k]
__device__ __half g_WsT[CC * CC];
__device__ __half g_WzT[CC * CZ];

// ---------------- smem layout (bytes) ----------------
// A: 128 rows x 392 halves (784 B/row, pad -> conflict-free ldmatrix)
// Z: 128 rows x 136 halves (272 B/row)
// W: 2 bufs x (128 rows x 136 halves)
constexpr uint32_t OFF_A  = 0;                       // 100352
constexpr uint32_t OFF_Z  = 100352;                  // +34816
constexpr uint32_t OFF_W  = 135168;                  // +2*34816
constexpr uint32_t OFF_SI = 204800;                  // 4x384 fp32
constexpr uint32_t OFF_SN = 210944;                  // 4x384 fp32
constexpr uint32_t OFF_M  = 217088;                  // 128 fp32
constexpr uint32_t SMEM_TOTAL = 217600;

constexpr int SA = 784;    // A row stride bytes
constexpr int SZ = 272;    // Z row stride bytes
constexpr int SW = 272;    // W row stride bytes
constexpr uint32_t WBUF_BYTES = 34816;

// ---------------- asm helpers ----------------
__device__ __forceinline__ uint32_t smem_u32(const void* p) {
    uint32_t a;
    asm("{ .reg .u64 t; cvta.to.shared.u64 t, %1; cvt.u32.u64 %0, t; }" : "=r"(a) : "l"(p));
    return a;
}
__device__ __forceinline__ void ldsm4(uint32_t& r0, uint32_t& r1, uint32_t& r2, uint32_t& r3,
                                      uint32_t addr) {
    asm volatile("ldmatrix.sync.aligned.m8n8.x4.shared.b16 {%0,%1,%2,%3}, [%4];"
                 : "=r"(r0), "=r"(r1), "=r"(r2), "=r"(r3) : "r"(addr));
}
__device__ __forceinline__ void mma16816(float* c, const uint32_t* a, const uint32_t* b) {
    asm volatile("mma.sync.aligned.m16n8k16.row.col.f32.f16.f16.f32 "
                 "{%0,%1,%2,%3}, {%4,%5,%6,%7}, {%8,%9}, {%0,%1,%2,%3};"
                 : "+f"(c[0]), "+f"(c[1]), "+f"(c[2]), "+f"(c[3])
                 : "r"(a[0]), "r"(a[1]), "r"(a[2]), "r"(a[3]), "r"(b[0]), "r"(b[1]));
}
__device__ __forceinline__ void cp16(uint32_t dst, const void* src) {
    asm volatile("cp.async.cg.shared.global [%0], [%1], 16;" :: "r"(dst), "l"(src));
}

// ---------------- weight fp32 -> fp16 transpose ----------------
__global__ void convert_w_t(const float* __restrict__ Ws, const float* __restrict__ Wz) {
    int i = blockIdx.x * blockDim.x + threadIdx.x;
    if (i < CC * CC) {
        int d = i / CC, k = i % CC;
        g_WsT[i] = __float2half_rn(Ws[k * CC + d]);
    }
    if (i < CC * CZ) {
        int d = i / CZ, k = i % CZ;
        g_WzT[i] = __float2half_rn(Wz[k * CC + d]);
    }
}

// ---------------- W staging (stage s: sub==0 -> Wz, else Ws k-chunk) ----------------
__device__ __forceinline__ void issue_w_load(int s, uint32_t dstBase, int tid) {
    const int sub = s & 3, d0 = (s >> 2) * 128;
    const __half* src;
    int rstride;
    if (sub == 0) { src = g_WzT + (size_t)d0 * CZ; rstride = CZ; }
    else          { src = g_WsT + (size_t)d0 * CC + (sub - 1) * 128; rstride = CC; }
    #pragma unroll
    for (int i = 0; i < 8; i++) {
        int idx = tid + i * 256;
        int r = idx >> 4, c = idx & 15;
        cp16(dstBase + r * SW + c * 16, src + (size_t)r * rstride + c * 8);
    }
    asm volatile("cp.async.commit_group;");
}

// ---------------- one GEMM stage: acc += A(128xk128) @ W(128n x 128k)^T ----------------
__device__ __forceinline__ void gemm_stage(uint32_t aLane, int aMfStride, uint32_t wLane,
                                           float (&acc)[2][8][4], bool zero) {
    if (zero) {
        #pragma unroll
        for (int mf = 0; mf < 2; mf++)
            #pragma unroll
            for (int nf = 0; nf < 8; nf++)
                #pragma unroll
                for (int e = 0; e < 4; e++) acc[mf][nf][e] = 0.f;
    }
    #pragma unroll
    for (int k = 0; k < 8; k++) {
        uint32_t a[2][4];
        #pragma unroll
        for (int mf = 0; mf < 2; mf++)
            ldsm4(a[mf][0], a[mf][1], a[mf][2], a[mf][3], aLane + mf * aMfStride + k * 32);
        uint32_t b[8][2];
        #pragma unroll
        for (int fp = 0; fp < 4; fp++) {
            uint32_t r0, r1, r2, r3;
            ldsm4(r0, r1, r2, r3, wLane + fp * (16 * SW) + k * 32);
            b[2 * fp][0] = r0; b[2 * fp][1] = r1;
            b[2 * fp + 1][0] = r2; b[2 * fp + 1][1] = r3;
        }
        #pragma unroll
        for (int mf = 0; mf < 2; mf++)
            #pragma unroll
            for (int nf = 0; nf < 8; nf++)
                mma16816(acc[mf][nf], a[mf], b[nf]);
    }
}

// ---------------- fused main kernel ----------------
__global__ void __launch_bounds__(256, 1) fused_kernel(
    const float* __restrict__ s_i,
    const float* __restrict__ s_ij,
    const float* __restrict__ m_ij,
    const float* __restrict__ z_ij,
    const float* __restrict__ gamma,
    const float* __restrict__ beta,
    float* __restrict__ out)
{
    extern __shared__ char smem[];
    const uint32_t sb = smem_u32(smem);
    const int tid = threadIdx.x, warp = tid >> 5, lane = tid & 31;
    const int wm = warp & 3, wn = warp >> 2;
    const int bn0 = blockIdx.x * NPC;

    // ---- prefetch W stages 0 and 1 via cp.async (overlaps with conversions below)
    issue_w_load(0, sb + OFF_W, tid);
    issue_w_load(1, sb + OFF_W + WBUF_BYTES, tid);

    // ---- load & convert A = s_ij (128 x 384) fp32 -> fp16 padded rows
    {
        const float4* g = (const float4*)(s_ij + (size_t)bn0 * NBR * CC);
        for (int idx = tid; idx < 6144; idx += 256) {
            int r = idx / 48, gcol = idx % 48;
            float4 v0 = g[r * 96 + gcol * 2];
            float4 v1 = g[r * 96 + gcol * 2 + 1];
            __half2 h0 = __floats2half2_rn(v0.x, v0.y), h1 = __floats2half2_rn(v0.z, v0.w);
            __half2 h2 = __floats2half2_rn(v1.x, v1.y), h3 = __floats2half2_rn(v1.z, v1.w);
            uint4 u;
            u.x = *(uint32_t*)&h0; u.y = *(uint32_t*)&h1;
            u.z = *(uint32_t*)&h2; u.w = *(uint32_t*)&h3;
            *(uint4*)(smem + OFF_A + r * SA + gcol * 16) = u;
        }
    }
    // ---- load & convert Z = z_ij (128 x 128)
    {
        const float4* g = (const float4*)(z_ij + (size_t)bn0 * NBR * CZ);
        for (int idx = tid; idx < 2048; idx += 256) {
            int r = idx >> 4, c = idx & 15;
            float4 v0 = g[r * 32 + c * 2];
            float4 v1 = g[r * 32 + c * 2 + 1];
            __half2 h0 = __floats2half2_rn(v0.x, v0.y), h1 = __floats2half2_rn(v0.z, v0.w);
            __half2 h2 = __floats2half2_rn(v1.x, v1.y), h3 = __floats2half2_rn(v1.z, v1.w);
            uint4 u;
            u.x = *(uint32_t*)&h0; u.y = *(uint32_t*)&h1;
            u.z = *(uint32_t*)&h2; u.w = *(uint32_t*)&h3;
            *(uint4*)(smem + OFF_Z + r * SZ + c * 16) = u;
        }
    }
    // ---- s_i, mask
    {
        const float4* g = (const float4*)(s_i + (size_t)bn0 * CC);
        float4* d = (float4*)(smem + OFF_SI);
        for (int idx = tid; idx < NPC * CC / 4; idx += 256) d[idx] = g[idx];
        if (tid < ROWS) ((float*)(smem + OFF_M))[tid] = m_ij[(size_t)bn0 * NBR + tid];
    }
    asm volatile("cp.async.wait_group 0;" ::: "memory");
    __syncthreads();

    // ---- lane-resolved base addresses for ldmatrix
    const uint32_t aA = sb + OFF_A + (32 * wm + (lane & 15)) * SA + (lane >> 4) * 16;
    const uint32_t aZ = sb + OFF_Z + (32 * wm + (lane & 15)) * SZ + (lane >> 4) * 16;
    const int g8 = lane >> 3;
    const uint32_t wOfs = (uint32_t)((64 * wn + (g8 >> 1) * 8 + (lane & 7)) * SW + (g8 & 1) * 16);

    float cG[2][8][4], cP[2][8][4];

    const float* M_s  = (const float*)(smem + OFF_M);
    const float* SI_s = (const float*)(smem + OFF_SI);
    float*       SN_s = (float*)(smem + OFF_SN);
    const float mv00 = M_s[32 * wm + (lane >> 2)];
    const float mv01 = M_s[32 * wm + (lane >> 2) + 8];
    const float mv10 = M_s[32 * wm + 16 + (lane >> 2)];
    const float mv11 = M_s[32 * wm + 16 + (lane >> 2) + 8];

    for (int s = 0; s < 12; ++s) {
        const int sub = s & 3, dt = s >> 2;
        const uint32_t wbuf = sb + OFF_W + (uint32_t)(s & 1) * WBUF_BYTES + wOfs;

        if (sub == 0) gemm_stage(aZ, 16 * SZ, wbuf, cG, true);
        else          gemm_stage(aA + (sub - 1) * 256, 16 * SA, wbuf, cP, sub == 1);

        if (sub == 3) {
            // epilogue: msg = m*(P - s_i)*G, reduce over 32 rows (this warp's n-pair)
            const int d0 = dt * 128;
            #pragma unroll
            for (int nf = 0; nf < 8; nf++) {
                const int col0 = d0 + 64 * wn + nf * 8 + (lane & 3) * 2;
                const float si0 = SI_s[wm * CC + col0];
                const float si1 = SI_s[wm * CC + col0 + 1];
                float t0 = mv00 * (cP[0][nf][0] - si0) * cG[0][nf][0]
                         + mv01 * (cP[0][nf][2] - si0) * cG[0][nf][2]
                         + mv10 * (cP[1][nf][0] - si0) * cG[1][nf][0]
                         + mv11 * (cP[1][nf][2] - si0) * cG[1][nf][2];
                float t1 = mv00 * (cP[0][nf][1] - si1) * cG[0][nf][1]
                         + mv01 * (cP[0][nf][3] - si1) * cG[0][nf][3]
                         + mv10 * (cP[1][nf][1] - si1) * cG[1][nf][1]
                         + mv11 * (cP[1][nf][3] - si1) * cG[1][nf][3];
                #pragma unroll
                for (int o = 4; o <= 16; o <<= 1) {
                    t0 += __shfl_xor_sync(0xffffffffu, t0, o);
                    t1 += __shfl_xor_sync(0xffffffffu, t1, o);
                }
                if ((lane >> 2) == 0) {
                    SN_s[wm * CC + col0]     = t0;
                    SN_s[wm * CC + col0 + 1] = t1;
                }
            }
        }
        __syncthreads();                              // all warps done with wbuf(s&1)
        if (s + 2 < 12) issue_w_load(s + 2, sb + OFF_W + (uint32_t)(s & 1) * WBUF_BYTES, tid);
        if (s + 1 < 12) {
            if (s + 2 < 12) asm volatile("cp.async.wait_group 1;" ::: "memory");
            else            asm volatile("cp.async.wait_group 0;" ::: "memory");
            __syncthreads();                          // stage s+1 visible to all
        }
    }

    // ---- fused layernorm: warp w handles (b,n) pair w
    if (warp < 4) {
        const float* x = SN_s + warp * CC;
        float v[12], sm = 0.f, sq = 0.f;
        #pragma unroll
        for (int j = 0; j < 12; j++) {
            v[j] = x[lane + j * 32];
            sm += v[j]; sq += v[j] * v[j];
        }
        #pragma unroll
        for (int o = 16; o; o >>= 1) {
            sm += __shfl_xor_sync(0xffffffffu, sm, o);
            sq += __shfl_xor_sync(0xffffffffu, sq, o);
        }
        const float mu = sm * (1.0f / CC);
        const float var = sq * (1.0f / CC) - mu * mu;
        const float rstd = rsqrtf(var + 1e-6f);
        float* o_ = out + (size_t)(bn0 + warp) * CC;
        #pragma unroll
        for (int j = 0; j < 12; j++) {
            int e = lane + j * 32;
            o_[e] = (v[j] - mu) * rstd * gamma[e] + beta[e];
        }
    }
}

// ---------------- launch ----------------
extern "C" void kernel_launch(void* const* d_in, const int* in_sizes, int n_in,
                              void* d_out, int out_size)
{
    const float* s_i   = (const float*)d_in[0];
    const float* s_ij  = (const float*)d_in[1];
    const float* m_ij  = (const float*)d_in[2];
    const float* z_ij  = (const float*)d_in[3];
    const float* W_s   = (const float*)d_in[4];
    const float* W_z   = (const float*)d_in[5];
    const float* gamma = (const float*)d_in[6];
    const float* beta  = (const float*)d_in[7];
    float* out = (float*)d_out;

    cudaFuncSetAttribute(fused_kernel, cudaFuncAttributeMaxDynamicSharedMemorySize,
                         (int)SMEM_TOTAL);

    convert_w_t<<<(CC * CC + 255) / 256, 256>>>(W_s, W_z);
    fused_kernel<<<BN / NPC, 256, SMEM_TOTAL>>>(s_i, s_ij, m_ij, z_ij, gamma, beta, out);
}

// round 9
// speedup vs baseline: 2.3314x; 1.1047x over previous
#include <cuda_runtime.h>
#include <cuda_fp16.h>
#include <cstdint>

// ---------------- problem shapes ----------------
constexpr int NBR = 32;
constexpr int CC  = 384;
constexpr int CZ  = 128;
constexpr int NPC = 4;            // (b,n) pairs per CTA
constexpr int ROWS = NPC * NBR;   // 128 = M
constexpr int BN = 4096;
constexpr int THREADS = 512;      // 16 warps

// transposed fp16 weights: [d][k]
__device__ __half g_WsT[CC * CC];
__device__ __half g_WzT[CC * CZ];

// ---------------- smem layout (bytes) ----------------
constexpr uint32_t OFF_A  = 0;                       // 128 x 784B
constexpr uint32_t OFF_Z  = 100352;                  // 128 x 272B
constexpr uint32_t OFF_W  = 135168;                  // 2 x 34816
constexpr uint32_t OFF_SI = 204800;                  // 4x384 fp32
constexpr uint32_t OFF_SN = 210944;                  // 4x384 fp32
constexpr uint32_t OFF_M  = 217088;                  // 128 fp32
constexpr uint32_t SMEM_TOTAL = 217600;

constexpr int SA = 784;    // A row stride bytes
constexpr int SZ = 272;    // Z row stride bytes
constexpr int SW = 272;    // W row stride bytes
constexpr uint32_t WBUF_BYTES = 34816;

// ---------------- asm helpers ----------------
__device__ __forceinline__ uint32_t smem_u32(const void* p) {
    uint32_t a;
    asm("{ .reg .u64 t; cvta.to.shared.u64 t, %1; cvt.u32.u64 %0, t; }" : "=r"(a) : "l"(p));
    return a;
}
__device__ __forceinline__ void ldsm4(uint32_t& r0, uint32_t& r1, uint32_t& r2, uint32_t& r3,
                                      uint32_t addr) {
    asm volatile("ldmatrix.sync.aligned.m8n8.x4.shared.b16 {%0,%1,%2,%3}, [%4];"
                 : "=r"(r0), "=r"(r1), "=r"(r2), "=r"(r3) : "r"(addr));
}
__device__ __forceinline__ void mma16816(float* c, const uint32_t* a, const uint32_t* b) {
    asm volatile("mma.sync.aligned.m16n8k16.row.col.f32.f16.f16.f32 "
                 "{%0,%1,%2,%3}, {%4,%5,%6,%7}, {%8,%9}, {%0,%1,%2,%3};"
                 : "+f"(c[0]), "+f"(c[1]), "+f"(c[2]), "+f"(c[3])
                 : "r"(a[0]), "r"(a[1]), "r"(a[2]), "r"(a[3]), "r"(b[0]), "r"(b[1]));
}
__device__ __forceinline__ void cp16(uint32_t dst, const void* src) {
    asm volatile("cp.async.cg.shared.global [%0], [%1], 16;" :: "r"(dst), "l"(src));
}

// ---------------- weight fp32 -> fp16 transpose ----------------
__global__ void convert_w_t(const float* __restrict__ Ws, const float* __restrict__ Wz) {
    int i = blockIdx.x * blockDim.x + threadIdx.x;
    if (i < CC * CC) {
        int d = i / CC, k = i % CC;
        g_WsT[i] = __float2half_rn(Ws[k * CC + d]);
    }
    if (i < CC * CZ) {
        int d = i / CZ, k = i % CZ;
        g_WzT[i] = __float2half_rn(Wz[k * CC + d]);
    }
}

// ---------------- W staging (stage s: sub==0 -> Wz, else Ws k-chunk) ----------------
__device__ __forceinline__ void issue_w_load(int s, uint32_t dstBase, int tid) {
    const int sub = s & 3, d0 = (s >> 2) * 128;
    const __half* src;
    int rstride;
    if (sub == 0) { src = g_WzT + (size_t)d0 * CZ; rstride = CZ; }
    else          { src = g_WsT + (size_t)d0 * CC + (sub - 1) * 128; rstride = CC; }
    #pragma unroll
    for (int i = 0; i < 4; i++) {
        int idx = tid + i * THREADS;
        int r = idx >> 4, c = idx & 15;
        cp16(dstBase + r * SW + c * 16, src + (size_t)r * rstride + c * 8);
    }
    asm volatile("cp.async.commit_group;");
}

// ---------------- one GEMM stage: acc += A(32m x 128k) @ W(32n x 128k)^T ----------------
__device__ __forceinline__ void gemm_stage(uint32_t aLane, int aMfStride, uint32_t wLane,
                                           float (&acc)[2][4][4], bool zero) {
    if (zero) {
        #pragma unroll
        for (int mf = 0; mf < 2; mf++)
            #pragma unroll
            for (int nf = 0; nf < 4; nf++)
                #pragma unroll
                for (int e = 0; e < 4; e++) acc[mf][nf][e] = 0.f;
    }
    #pragma unroll
    for (int k = 0; k < 8; k++) {
        uint32_t a[2][4];
        #pragma unroll
        for (int mf = 0; mf < 2; mf++)
            ldsm4(a[mf][0], a[mf][1], a[mf][2], a[mf][3], aLane + mf * aMfStride + k * 32);
        uint32_t b[4][2];
        #pragma unroll
        for (int fp = 0; fp < 2; fp++) {
            uint32_t r0, r1, r2, r3;
            ldsm4(r0, r1, r2, r3, wLane + fp * (16 * SW) + k * 32);
            b[2 * fp][0] = r0; b[2 * fp][1] = r1;
            b[2 * fp + 1][0] = r2; b[2 * fp + 1][1] = r3;
        }
        #pragma unroll
        for (int mf = 0; mf < 2; mf++)
            #pragma unroll
            for (int nf = 0; nf < 4; nf++)
                mma16816(acc[mf][nf], a[mf], b[nf]);
    }
}

// ---------------- fused main kernel ----------------
__global__ void __launch_bounds__(THREADS, 1) fused_kernel(
    const float* __restrict__ s_i,
    const float* __restrict__ s_ij,
    const float* __restrict__ m_ij,
    const float* __restrict__ z_ij,
    const float* __restrict__ gamma,
    const float* __restrict__ beta,
    float* __restrict__ out)
{
    extern __shared__ char smem[];
    const uint32_t sb = smem_u32(smem);
    const int tid = threadIdx.x, warp = tid >> 5, lane = tid & 31;
    const int wm = warp & 3, wn = warp >> 2;      // 4 x 4 warp grid
    const int bn0 = blockIdx.x * NPC;

    // ---- prefetch W stages 0 and 1 via cp.async
    issue_w_load(0, sb + OFF_W, tid);
    issue_w_load(1, sb + OFF_W + WBUF_BYTES, tid);

    // ---- load & convert Z = z_ij (128 x 128)
    {
        const float4* g = (const float4*)(z_ij + (size_t)bn0 * NBR * CZ);
        #pragma unroll
        for (int i = 0; i < 4; i++) {
            int idx = tid + i * THREADS;
            int r = idx >> 4, c = idx & 15;
            float4 v0 = g[r * 32 + c * 2];
            float4 v1 = g[r * 32 + c * 2 + 1];
            __half2 h0 = __floats2half2_rn(v0.x, v0.y), h1 = __floats2half2_rn(v0.z, v0.w);
            __half2 h2 = __floats2half2_rn(v1.x, v1.y), h3 = __floats2half2_rn(v1.z, v1.w);
            uint4 u;
            u.x = *(uint32_t*)&h0; u.y = *(uint32_t*)&h1;
            u.z = *(uint32_t*)&h2; u.w = *(uint32_t*)&h3;
            *(uint4*)(smem + OFF_Z + r * SZ + c * 16) = u;
        }
    }
    // ---- s_i, mask
    {
        const float4* g = (const float4*)(s_i + (size_t)bn0 * CC);
        float4* d = (float4*)(smem + OFF_SI);
        if (tid < NPC * CC / 4) d[tid] = g[tid];
        if (tid < ROWS) ((float*)(smem + OFF_M))[tid] = m_ij[(size_t)bn0 * NBR + tid];
    }
    asm volatile("cp.async.wait_group 0;" ::: "memory");   // W0, W1 resident
    __syncthreads();                                       // Z / si / mask visible

    // ---- lane-resolved base addresses
    const uint32_t aA = sb + OFF_A + (32 * wm + (lane & 15)) * SA + (lane >> 4) * 16;
    const uint32_t aZ = sb + OFF_Z + (32 * wm + (lane & 15)) * SZ + (lane >> 4) * 16;
    const int g8 = lane >> 3;
    const uint32_t wOfs = (uint32_t)((32 * wn + (g8 >> 1) * 8 + (lane & 7)) * SW + (g8 & 1) * 16);

    float cG[2][4][4], cP[2][4][4];

    const float* M_s  = (const float*)(smem + OFF_M);
    const float* SI_s = (const float*)(smem + OFF_SI);
    float*       SN_s = (float*)(smem + OFF_SN);
    const float mv00 = M_s[32 * wm + (lane >> 2)];
    const float mv01 = M_s[32 * wm + (lane >> 2) + 8];
    const float mv10 = M_s[32 * wm + 16 + (lane >> 2)];
    const float mv11 = M_s[32 * wm + 16 + (lane >> 2) + 8];

    // ==== phase B: per-warp A-convert slice, then GEMM2 (dt=0) — no barrier between,
    //      so A-load latency of some warps hides under other warps' MMA issue.
    {
        const float4* g = (const float4*)(s_ij + (size_t)bn0 * NBR * CC);
        #pragma unroll
        for (int j = 0; j < 12; j++) {
            int idx = warp * 384 + j * 32 + lane;   // this warp: rows [8*warp, 8*warp+8)
            int r = idx / 48, gcol = idx % 48;
            float4 v0 = g[r * 96 + gcol * 2];
            float4 v1 = g[r * 96 + gcol * 2 + 1];
            __half2 h0 = __floats2half2_rn(v0.x, v0.y), h1 = __floats2half2_rn(v0.z, v0.w);
            __half2 h2 = __floats2half2_rn(v1.x, v1.y), h3 = __floats2half2_rn(v1.z, v1.w);
            uint4 u;
            u.x = *(uint32_t*)&h0; u.y = *(uint32_t*)&h1;
            u.z = *(uint32_t*)&h2; u.w = *(uint32_t*)&h3;
            *(uint4*)(smem + OFF_A + r * SA + gcol * 16) = u;
        }
        gemm_stage(aZ, 16 * SZ, sb + OFF_W + wOfs, cG, true);   // stage 0 (Wz, dt=0)
    }
    __syncthreads();                       // A complete everywhere; W buf0 free
    issue_w_load(2, sb + OFF_W, tid);      // stage 2 -> buf0

    // ==== stages 1..11 (stage s uses buf s&1; stage s+1 already resident/in-flight)
    for (int s = 1; s < 12; ++s) {
        const int sub = s & 3, dt = s >> 2;
        const uint32_t wbuf = sb + OFF_W + (uint32_t)(s & 1) * WBUF_BYTES + wOfs;

        if (sub == 0) gemm_stage(aZ, 16 * SZ, wbuf, cG, true);
        else          gemm_stage(aA + (sub - 1) * 256, 16 * SA, wbuf, cP, sub == 1);

        if (sub == 3) {
            // epilogue: msg = m*(P - s_i)*G, reduce over this warp's 32 neighbor rows
            const int d0 = dt * 128;
            #pragma unroll
            for (int nf = 0; nf < 4; nf++) {
                const int col0 = d0 + 32 * wn + nf * 8 + (lane & 3) * 2;
                const float si0 = SI_s[wm * CC + col0];
                const float si1 = SI_s[wm * CC + col0 + 1];
                float t0 = mv00 * (cP[0][nf][0] - si0) * cG[0][nf][0]
                         + mv01 * (cP[0][nf][2] - si0) * cG[0][nf][2]
                         + mv10 * (cP[1][nf][0] - si0) * cG[1][nf][0]
                         + mv11 * (cP[1][nf][2] - si0) * cG[1][nf][2];
                float t1 = mv00 * (cP[0][nf][1] - si1) * cG[0][nf][1]
                         + mv01 * (cP[0][nf][3] - si1) * cG[0][nf][3]
                         + mv10 * (cP[1][nf][1] - si1) * cG[1][nf][1]
                         + mv11 * (cP[1][nf][3] - si1) * cG[1][nf][3];
                #pragma unroll
                for (int o = 4; o <= 16; o <<= 1) {
                    t0 += __shfl_xor_sync(0xffffffffu, t0, o);
                    t1 += __shfl_xor_sync(0xffffffffu, t1, o);
                }
                if ((lane >> 2) == 0) {
                    SN_s[wm * CC + col0]     = t0;
                    SN_s[wm * CC + col0 + 1] = t1;
                }
            }
        }
        __syncthreads();                              // all warps done with buf(s&1)
        if (s + 2 < 12) issue_w_load(s + 2, sb + OFF_W + (uint32_t)(s & 1) * WBUF_BYTES, tid);
        if (s + 1 < 12) {
            if (s + 2 < 12) asm volatile("cp.async.wait_group 1;" ::: "memory");
            else            asm volatile("cp.async.wait_group 0;" ::: "memory");
            __syncthreads();                          // stage s+1 visible
        }
    }

    // ---- fused layernorm: warp w handles (b,n) pair w
    if (warp < 4) {
        const float* x = SN_s + warp * CC;
        float v[12], sm = 0.f, sq = 0.f;
        #pragma unroll
        for (int j = 0; j < 12; j++) {
            v[j] = x[lane + j * 32];
            sm += v[j]; sq += v[j] * v[j];
        }
        #pragma unroll
        for (int o = 16; o; o >>= 1) {
            sm += __shfl_xor_sync(0xffffffffu, sm, o);
            sq += __shfl_xor_sync(0xffffffffu, sq, o);
        }
        const float mu = sm * (1.0f / CC);
        const float var = sq * (1.0f / CC) - mu * mu;
        const float rstd = rsqrtf(var + 1e-6f);
        float* o_ = out + (size_t)(bn0 + warp) * CC;
        #pragma unroll
        for (int j = 0; j < 12; j++) {
            int e = lane + j * 32;
            o_[e] = (v[j] - mu) * rstd * gamma[e] + beta[e];
        }
    }
}

// ---------------- launch ----------------
extern "C" void kernel_launch(void* const* d_in, const int* in_sizes, int n_in,
                              void* d_out, int out_size)
{
    const float* s_i   = (const float*)d_in[0];
    const float* s_ij  = (const float*)d_in[1];
    const float* m_ij  = (const float*)d_in[2];
    const float* z_ij  = (const float*)d_in[3];
    const float* W_s   = (const float*)d_in[4];
    const float* W_z   = (const float*)d_in[5];
    const float* gamma = (const float*)d_in[6];
    const float* beta  = (const float*)d_in[7];
    float* out = (float*)d_out;

    cudaFuncSetAttribute(fused_kernel, cudaFuncAttributeMaxDynamicSharedMemorySize,
                         (int)SMEM_TOTAL);

    convert_w_t<<<(CC * CC + 255) / 256, 256>>>(W_s, W_z);
    fused_kernel<<<BN / NPC, THREADS, SMEM_TOTAL>>>(s_i, s_ij, m_ij, z_ij, gamma, beta, out);
}

// round 11
// speedup vs baseline: 2.5296x; 1.0850x over previous
#include <cuda_runtime.h>
#include <cuda_fp16.h>
#include <cstdint>

// ---------------- problem shapes ----------------
constexpr int NBR = 32;
constexpr int CC  = 384;
constexpr int CZ  = 128;
constexpr int NPC = 4;            // (b,n) pairs per CTA
constexpr int ROWS = NPC * NBR;   // 128 = M
constexpr int BN = 4096;
constexpr int THREADS = 512;      // 16 warps = 2 groups x 8

// transposed fp16 weights: [d][k]
__device__ __half g_WsT[CC * CC];
__device__ __half g_WzT[CC * CZ];

// ---------------- smem layout (bytes) ----------------
constexpr uint32_t OFF_A  = 0;                       // 128 x 784B
constexpr uint32_t OFF_Z  = 100352;                  // 128 x 272B
constexpr uint32_t OFF_W  = 135168;                  // 2 grp x 2 buf x 17408
constexpr uint32_t OFF_SI = 204800;                  // 4x384 fp32
constexpr uint32_t OFF_SN = 210944;                  // 4x384 fp32
constexpr uint32_t OFF_M  = 217088;                  // 128 fp32
constexpr uint32_t SMEM_TOTAL = 217600;

constexpr int SA = 784;    // A row stride bytes
constexpr int SZ = 272;    // Z row stride bytes
constexpr int SW = 272;    // W row stride bytes
constexpr uint32_t WBUF = 17408;     // one buf: 64 rows x 272B
constexpr uint32_t WGRP = 34816;     // per-group region (2 bufs)

// ---------------- asm helpers ----------------
__device__ __forceinline__ uint32_t smem_u32(const void* p) {
    uint32_t a;
    asm("{ .reg .u64 t; cvta.to.shared.u64 t, %1; cvt.u32.u64 %0, t; }" : "=r"(a) : "l"(p));
    return a;
}
__device__ __forceinline__ void ldsm4(uint32_t& r0, uint32_t& r1, uint32_t& r2, uint32_t& r3,
                                      uint32_t addr) {
    asm volatile("ldmatrix.sync.aligned.m8n8.x4.shared.b16 {%0,%1,%2,%3}, [%4];"
                 : "=r"(r0), "=r"(r1), "=r"(r2), "=r"(r3) : "r"(addr));
}
__device__ __forceinline__ void mma16816(float* c, const uint32_t* a, const uint32_t* b) {
    asm volatile("mma.sync.aligned.m16n8k16.row.col.f32.f16.f16.f32 "
                 "{%0,%1,%2,%3}, {%4,%5,%6,%7}, {%8,%9}, {%0,%1,%2,%3};"
                 : "+f"(c[0]), "+f"(c[1]), "+f"(c[2]), "+f"(c[3])
                 : "r"(a[0]), "r"(a[1]), "r"(a[2]), "r"(a[3]), "r"(b[0]), "r"(b[1]));
}
__device__ __forceinline__ void cp16(uint32_t dst, const void* src) {
    asm volatile("cp.async.cg.shared.global [%0], [%1], 16;" :: "r"(dst), "l"(src));
}
__device__ __forceinline__ void bar_grp(int id) {
    asm volatile("bar.sync %0, 256;" :: "r"(id) : "memory");
}

// ---------------- weight fp32 -> fp16 transpose ----------------
__global__ void convert_w_t(const float* __restrict__ Ws, const float* __restrict__ Wz) {
    int i = blockIdx.x * blockDim.x + threadIdx.x;
    if (i < CC * CC) {
        int d = i / CC, k = i % CC;
        g_WsT[i] = __float2half_rn(Ws[k * CC + d]);
    }
    if (i < CC * CZ) {
        int d = i / CZ, k = i % CZ;
        g_WzT[i] = __float2half_rn(Wz[k * CC + d]);
    }
}

// ---------------- W staging: group grp loads its 64-row slice of stage s ----------------
__device__ __forceinline__ void issue_w_load(int s, int grp, uint32_t dstBase, int gtid) {
    const int sub = s & 3, d0 = (s >> 2) * 128;
    const __half* src;
    int rstride;
    if (sub == 0) { src = g_WzT + (size_t)(d0 + grp * 64) * CZ; rstride = CZ; }
    else          { src = g_WsT + (size_t)(d0 + grp * 64) * CC + (sub - 1) * 128; rstride = CC; }
    #pragma unroll
    for (int i = 0; i < 4; i++) {
        int idx = gtid + i * 256;          // 0..1023 : 64 rows x 16 int4
        int r = idx >> 4, c = idx & 15;
        cp16(dstBase + r * SW + c * 16, src + (size_t)r * rstride + c * 8);
    }
    asm volatile("cp.async.commit_group;");
}

// ---------------- one GEMM stage: acc += A(32m x 128k) @ W(32n x 128k)^T ----------------
__device__ __forceinline__ void gemm_stage(uint32_t aLane, int aMfStride, uint32_t wLane,
                                           float (&acc)[2][4][4], bool zero) {
    if (zero) {
        #pragma unroll
        for (int mf = 0; mf < 2; mf++)
            #pragma unroll
            for (int nf = 0; nf < 4; nf++)
                #pragma unroll
                for (int e = 0; e < 4; e++) acc[mf][nf][e] = 0.f;
    }
    #pragma unroll
    for (int k = 0; k < 8; k++) {
        uint32_t a[2][4];
        #pragma unroll
        for (int mf = 0; mf < 2; mf++)
            ldsm4(a[mf][0], a[mf][1], a[mf][2], a[mf][3], aLane + mf * aMfStride + k * 32);
        uint32_t b[4][2];
        #pragma unroll
        for (int fp = 0; fp < 2; fp++) {
            uint32_t r0, r1, r2, r3;
            ldsm4(r0, r1, r2, r3, wLane + fp * (16 * SW) + k * 32);
            b[2 * fp][0] = r0; b[2 * fp][1] = r1;
            b[2 * fp + 1][0] = r2; b[2 * fp + 1][1] = r3;
        }
        #pragma unroll
        for (int mf = 0; mf < 2; mf++)
            #pragma unroll
            for (int nf = 0; nf < 4; nf++)
                mma16816(acc[mf][nf], a[mf], b[nf]);
    }
}

// ---------------- fused main kernel ----------------
__global__ void __launch_bounds__(THREADS, 1) fused_kernel(
    const float* __restrict__ s_i,
    const float* __restrict__ s_ij,
    const float* __restrict__ m_ij,
    const float* __restrict__ z_ij,
    const float* __restrict__ gamma,
    const float* __restrict__ beta,
    float* __restrict__ out)
{
    extern __shared__ char smem[];
    const uint32_t sb = smem_u32(smem);
    const int tid = threadIdx.x, warp = tid >> 5, lane = tid & 31;
    const int grp = warp >> 3;            // pipeline group 0/1 (owns 64 output cols)
    const int gwarp = warp & 7;
    const int wm = gwarp & 3, wn2 = gwarp >> 2;   // 4m x 2n within group
    const int gtid = tid & 255;
    const int bn0 = blockIdx.x * NPC;
    const uint32_t wgbase = sb + OFF_W + (uint32_t)grp * WGRP;

    // ---- prefetch this group's W stages 0 and 1
    issue_w_load(0, grp, wgbase, gtid);
    issue_w_load(1, grp, wgbase + WBUF, gtid);

    // ---- load & convert Z = z_ij (128 x 128), shared by both groups
    {
        const float4* g = (const float4*)(z_ij + (size_t)bn0 * NBR * CZ);
        #pragma unroll
        for (int i = 0; i < 4; i++) {
            int idx = tid + i * THREADS;
            int r = idx >> 4, c = idx & 15;
            float4 v0 = g[r * 32 + c * 2];
            float4 v1 = g[r * 32 + c * 2 + 1];
            __half2 h0 = __floats2half2_rn(v0.x, v0.y), h1 = __floats2half2_rn(v0.z, v0.w);
            __half2 h2 = __floats2half2_rn(v1.x, v1.y), h3 = __floats2half2_rn(v1.z, v1.w);
            uint4 u;
            u.x = *(uint32_t*)&h0; u.y = *(uint32_t*)&h1;
            u.z = *(uint32_t*)&h2; u.w = *(uint32_t*)&h3;
            *(uint4*)(smem + OFF_Z + r * SZ + c * 16) = u;
        }
    }
    // ---- s_i, mask
    {
        const float4* g = (const float4*)(s_i + (size_t)bn0 * CC);
        float4* d = (float4*)(smem + OFF_SI);
        if (tid < NPC * CC / 4) d[tid] = g[tid];
        if (tid < ROWS) ((float*)(smem + OFF_M))[tid] = m_ij[(size_t)bn0 * NBR + tid];
    }
    asm volatile("cp.async.wait_group 0;" ::: "memory");   // W0, W1 resident (this thread's grp)
    __syncthreads();                                       // Z / si / mask visible

    // ---- lane-resolved base addresses
    const uint32_t aA = sb + OFF_A + (32 * wm + (lane & 15)) * SA + (lane >> 4) * 16;
    const uint32_t aZ = sb + OFF_Z + (32 * wm + (lane & 15)) * SZ + (lane >> 4) * 16;
    const int g8 = lane >> 3;
    const uint32_t wOfs = (uint32_t)((32 * wn2 + (g8 >> 1) * 8 + (lane & 7)) * SW + (g8 & 1) * 16);

    float cG[2][4][4], cP[2][4][4];

    const float* M_s  = (const float*)(smem + OFF_M);
    const float* SI_s = (const float*)(smem + OFF_SI);
    float*       SN_s = (float*)(smem + OFF_SN);
    const float mv00 = M_s[32 * wm + (lane >> 2)];
    const float mv01 = M_s[32 * wm + (lane >> 2) + 8];
    const float mv10 = M_s[32 * wm + 16 + (lane >> 2)];
    const float mv11 = M_s[32 * wm + 16 + (lane >> 2) + 8];

    // ==== phase B: per-warp A-convert slice, then GEMM2 stage 0 — no barrier between,
    //      so A-load latency hides under other warps' MMA issue.
    {
        const float4* g = (const float4*)(s_ij + (size_t)bn0 * NBR * CC);
        #pragma unroll
        for (int j = 0; j < 12; j++) {
            int idx = warp * 384 + j * 32 + lane;   // this warp: rows [8*warp, 8*warp+8)
            int r = idx / 48, gcol = idx % 48;
            float4 v0 = g[r * 96 + gcol * 2];
            float4 v1 = g[r * 96 + gcol * 2 + 1];
            __half2 h0 = __floats2half2_rn(v0.x, v0.y), h1 = __floats2half2_rn(v0.z, v0.w);
            __half2 h2 = __floats2half2_rn(v1.x, v1.y), h3 = __floats2half2_rn(v1.z, v1.w);
            uint4 u;
            u.x = *(uint32_t*)&h0; u.y = *(uint32_t*)&h1;
            u.z = *(uint32_t*)&h2; u.w = *(uint32_t*)&h3;
            *(uint4*)(smem + OFF_A + r * SA + gcol * 16) = u;
        }
        gemm_stage(aZ, 16 * SZ, wgbase + wOfs, cG, true);   // stage 0 (Wz slice, dt=0)
    }
    __syncthreads();                          // A complete everywhere; buf0 free (both grps)
    issue_w_load(2, grp, wgbase, gtid);       // stage 2 -> this group's buf0

    // ==== stages 1..11 — each group pipelines independently (named barriers)
    for (int s = 1; s < 12; ++s) {
        const int sub = s & 3, dt = s >> 2;
        const uint32_t wbuf = wgbase + (uint32_t)(s & 1) * WBUF + wOfs;

        if (sub == 0) gemm_stage(aZ, 16 * SZ, wbuf, cG, true);
        else          gemm_stage(aA + (sub - 1) * 256, 16 * SA, wbuf, cP, sub == 1);

        if (sub == 3) {
            // epilogue: msg = m*(P - s_i)*G, reduce over this warp's 32 neighbor rows
            const int d0 = dt * 128;
            #pragma unroll
            for (int nf = 0; nf < 4; nf++) {
                const int col0 = d0 + grp * 64 + 32 * wn2 + nf * 8 + (lane & 3) * 2;
                const float si0 = SI_s[wm * CC + col0];
                const float si1 = SI_s[wm * CC + col0 + 1];
                float t0 = mv00 * (cP[0][nf][0] - si0) * cG[0][nf][0]
                         + mv01 * (cP[0][nf][2] - si0) * cG[0][nf][2]
                         + mv10 * (cP[1][nf][0] - si0) * cG[1][nf][0]
                         + mv11 * (cP[1][nf][2] - si0) * cG[1][nf][2];
                float t1 = mv00 * (cP[0][nf][1] - si1) * cG[0][nf][1]
                         + mv01 * (cP[0][nf][3] - si1) * cG[0][nf][3]
                         + mv10 * (cP[1][nf][1] - si1) * cG[1][nf][1]
                         + mv11 * (cP[1][nf][3] - si1) * cG[1][nf][3];
                #pragma unroll
                for (int o = 4; o <= 16; o <<= 1) {
                    t0 += __shfl_xor_sync(0xffffffffu, t0, o);
                    t1 += __shfl_xor_sync(0xffffffffu, t1, o);
                }
                if ((lane >> 2) == 0) {
                    SN_s[wm * CC + col0]     = t0;
                    SN_s[wm * CC + col0 + 1] = t1;
                }
            }
        }
        bar_grp(1 + grp);                      // this group done with buf(s&1)
        if (s + 2 < 12) issue_w_load(s + 2, grp, wgbase + (uint32_t)(s & 1) * WBUF, gtid);
        if (s + 1 < 12) {
            if (s + 2 < 12) asm volatile("cp.async.wait_group 1;" ::: "memory");
            else            asm volatile("cp.async.wait_group 0;" ::: "memory");
            bar_grp(1 + grp);                  // stage s+1 visible to this group
        }
    }

    // ---- fused layernorm: needs SN from both groups
    __syncthreads();
    if (warp < 4) {
        const float* x = SN_s + warp * CC;
        float v[12], sm = 0.f, sq = 0.f;
        #pragma unroll
        for (int j = 0; j < 12; j++) {
            v[j] = x[lane + j * 32];
            sm += v[j]; sq += v[j] * v[j];
        }
        #pragma unroll
        for (int o = 16; o; o >>= 1) {
            sm += __shfl_xor_sync(0xffffffffu, sm, o);
            sq += __shfl_xor_sync(0xffffffffu, sq, o);
        }
        const float mu = sm * (1.0f / CC);
        const float var = sq * (1.0f / CC) - mu * mu;
        const float rstd = rsqrtf(var + 1e-6f);
        float* o_ = out + (size_t)(bn0 + warp) * CC;
        #pragma unroll
        for (int j = 0; j < 12; j++) {
            int e = lane + j * 32;
            o_[e] = (v[j] - mu) * rstd * gamma[e] + beta[e];
        }
    }
}

// ---------------- launch ----------------
extern "C" void kernel_launch(void* const* d_in, const int* in_sizes, int n_in,
                              void* d_out, int out_size)
{
    const float* s_i   = (const float*)d_in[0];
    const float* s_ij  = (const float*)d_in[1];
    const float* m_ij  = (const float*)d_in[2];
    const float* z_ij  = (const float*)d_in[3];
    const float* W_s   = (const float*)d_in[4];
    const float* W_z   = (const float*)d_in[5];
    const float* gamma = (const float*)d_in[6];
    const float* beta  = (const float*)d_in[7];
    float* out = (float*)d_out;

    cudaFuncSetAttribute(fused_kernel, cudaFuncAttributeMaxDynamicSharedMemorySize,
                         (int)SMEM_TOTAL);

    convert_w_t<<<(CC * CC + 255) / 256, 256>>>(W_s, W_z);
    fused_kernel<<<BN / NPC, THREADS, SMEM_TOTAL>>>(s_i, s_ij, m_ij, z_ij, gamma, beta, out);
}